// round 8
// baseline (speedup 1.0000x reference)
#include <cuda_runtime.h>
#include <cuda_bf16.h>
#include <cstdint>

// Fixed shapes: [16, 4096, 2] fp32 both inputs
#define NOBJ 16
#define P    4096
#define BQ   128      // queries per CTA
#define BR   256      // refs staged per chunk
#define NCHUNK (P/BR)
#define EPSF 1e-12f

// Scratch (allocation-free)
static __device__ float g_sum1[NOBJ * 32];
static __device__ float g_sum2[NOBJ * 32];
static __device__ float g_cost[NOBJ];

// ---- packed fp32x2 helpers (FFMA2 is PTX-only; ptxas won't auto-fuse) ----
__device__ __forceinline__ unsigned long long pack2(float lo, float hi) {
    unsigned long long r;
    asm("mov.b64 %0, {%1, %2};" : "=l"(r) : "f"(lo), "f"(hi));
    return r;
}
__device__ __forceinline__ void unpack2(unsigned long long v, float& lo, float& hi) {
    asm("mov.b64 {%0, %1}, %2;" : "=f"(lo), "=f"(hi) : "l"(v));
}
__device__ __forceinline__ unsigned long long fma2(unsigned long long a,
                                                   unsigned long long b,
                                                   unsigned long long c) {
    unsigned long long d;
    asm("fma.rn.f32x2 %0, %1, %2, %3;" : "=l"(d) : "l"(a), "l"(b), "l"(c));
    return d;
}

// ---------------------------------------------------------------------------
// Both chamfer directions in ONE launch: dir = blockIdx.z.
// Per jj (8 pairs): 3 LDS.64 + 8 FFMA2 + 8 FMNMX.
// x2 (query norms) are NOT held across the mainloop — recomputed from sQ in
// the epilogue. This drops regs below 64 so 4 CTAs/SM fit (occupancy lever).
// ---------------------------------------------------------------------------
__global__ __launch_bounds__(256, 4) void k_pass(const float* __restrict__ pt1,
                                                 const float* __restrict__ pt2) {
    const int n = blockIdx.y, tile = blockIdx.x, tid = threadIdx.x;
    const int dir = blockIdx.z;
    const int tx = tid & 15, ty = tid >> 4;

    const float* q = dir ? pt2 : pt1;
    const float* r = dir ? pt1 : pt2;

    __shared__ unsigned long long sA[BR], sB[BR], sC[BR];
    __shared__ float2 sQ[BQ];
    __shared__ float  sRed[16];

    const float2* qp = reinterpret_cast<const float2*>(q) + n * P + tile * BQ;
    const float2* rp = reinterpret_cast<const float2*>(r) + n * P;

    if (tid < BQ) sQ[tid] = qp[tid];
    float2 ycur = rp[tid];               // prefetch chunk 0
    __syncthreads();

    unsigned long long m2a[4], m2b[4];
    float rmin[8];
    #pragma unroll
    for (int p = 0; p < 4; p++) {
        float2 xa = sQ[ty * 8 + 2 * p];
        float2 xb = sQ[ty * 8 + 2 * p + 1];
        m2a[p] = pack2(-2.0f * xa.x, -2.0f * xb.x);
        m2b[p] = pack2(-2.0f * xa.y, -2.0f * xb.y);
    }
    #pragma unroll
    for (int i = 0; i < 8; i++) rmin[i] = 3.402823466e38f;

    for (int jc = 0; jc < NCHUNK; jc++) {
        __syncthreads();                 // consumers done with previous chunk
        sA[tid] = pack2(ycur.x, ycur.x);
        sB[tid] = pack2(ycur.y, ycur.y);
        float yy = fmaf(ycur.x, ycur.x, ycur.y * ycur.y);
        sC[tid] = pack2(yy, yy);
        if (jc + 1 < NCHUNK) ycur = rp[(jc + 1) * BR + tid];  // overlap LDG
        __syncthreads();

        #pragma unroll
        for (int jj = 0; jj < BR / 16; jj++) {
            const int c = jj * 16 + tx;  // 8B stride -> conflict-free/broadcast
            const unsigned long long ya = sA[c];
            const unsigned long long yb = sB[c];
            const unsigned long long yc = sC[c];
            #pragma unroll
            for (int p = 0; p < 4; p++) {
                unsigned long long u2 = fma2(m2a[p], ya, yc);
                u2 = fma2(m2b[p], yb, u2);
                float u0, u1;
                unpack2(u2, u0, u1);
                rmin[2 * p]     = fminf(rmin[2 * p], u0);
                rmin[2 * p + 1] = fminf(rmin[2 * p + 1], u1);
            }
        }
    }

    // epilogue: min across the 16 tx lanes of each ty group, recompute x2 here
    float rs = 0.0f;
    #pragma unroll
    for (int i = 0; i < 8; i++) {
        float v = rmin[i];
        #pragma unroll
        for (int off = 8; off >= 1; off >>= 1)
            v = fminf(v, __shfl_xor_sync(0xffffffffu, v, off, 16));
        if (tx == 0) {
            float2 x = sQ[ty * 8 + i];
            float x2 = fmaf(x.x, x.x, x.y * x.y);
            rs += sqrtf(fmaxf(x2 + v, EPSF));
        }
    }
    if (tx == 0) sRed[ty] = rs;
    __syncthreads();
    if (tid == 0) {
        float s = 0.0f;
        #pragma unroll
        for (int t = 0; t < 16; t++) s += sRed[t];
        (dir ? g_sum2 : g_sum1)[n * 32 + tile] = s;
    }
}

// ---------------------------------------------------------------------------
// Finalize stage 1: one block per object (mask + per-object masked cost).
// ---------------------------------------------------------------------------
__global__ void k_final1(const float* __restrict__ pt2, float* __restrict__ unused) {
    __shared__ float sred[256];
    const int n = blockIdx.x, tid = threadIdx.x;

    float s = 0.0f;
    const float4* p = reinterpret_cast<const float4*>(pt2 + n * P * 2);
    #pragma unroll
    for (int i = 0; i < (P * 2 / 4) / 256; i++) {   // 8 independent loads
        float4 v = p[i * 256 + tid];
        s += (v.x + v.y) + (v.z + v.w);
    }
    sred[tid] = s;
    __syncthreads();
    #pragma unroll
    for (int st = 128; st > 0; st >>= 1) {
        if (tid < st) sred[tid] += sred[tid + st];
        __syncthreads();
    }
    if (tid == 0) {
        float mask = sred[0];
        float s1 = 0.0f, s2 = 0.0f;
        #pragma unroll
        for (int t = 0; t < 32; t++) {
            s1 += g_sum1[n * 32 + t];
            s2 += g_sum2[n * 32 + t];
        }
        g_cost[n] = (mask >= 0.0f) ? 0.5f * (s1 + s2) * (1.0f / P) : 0.0f;
    }
}

// Finalize stage 2: sum 16 per-object costs.
__global__ void k_final2(float* __restrict__ out) {
    if (threadIdx.x == 0) {
        float s = 0.0f;
        #pragma unroll
        for (int t = 0; t < NOBJ; t++) s += g_cost[t];
        out[0] = s * (1.0f / NOBJ);
    }
}

// ---------------------------------------------------------------------------
extern "C" void kernel_launch(void* const* d_in, const int* in_sizes, int n_in,
                              void* d_out, int out_size) {
    const float* pt1 = reinterpret_cast<const float*>(d_in[0]);
    const float* pt2 = reinterpret_cast<const float*>(d_in[1]);
    float* out = reinterpret_cast<float*>(d_out);
    (void)in_sizes; (void)n_in; (void)out_size;

    dim3 grid(P / BQ, NOBJ, 2);   // (32, 16, 2) — both directions, one launch
    k_pass<<<grid, 256>>>(pt1, pt2);
    k_final1<<<NOBJ, 256>>>(pt2, out);
    k_final2<<<1, 32>>>(out);
}

// round 11
// speedup vs baseline: 1.5882x; 1.5882x over previous
#include <cuda_runtime.h>
#include <cuda_bf16.h>
#include <cstdint>

// Fixed shapes: [16, 4096, 2] fp32 both inputs
#define NOBJ 16
#define P    4096
#define BQ   128      // queries per CTA
#define BR   256      // refs staged per chunk
#define NCHUNK (P/BR)
#define EPSF 1e-12f

// Scratch (allocation-free)
static __device__ float g_sum1[NOBJ * 32];
static __device__ float g_sum2[NOBJ * 32];
static __device__ float g_cost[NOBJ];

// ---- packed fp32x2 helpers (FFMA2 is PTX-only; ptxas won't auto-fuse) ----
__device__ __forceinline__ unsigned long long pack2(float lo, float hi) {
    unsigned long long r;
    asm("mov.b64 %0, {%1, %2};" : "=l"(r) : "f"(lo), "f"(hi));
    return r;
}
__device__ __forceinline__ void unpack2(unsigned long long v, float& lo, float& hi) {
    asm("mov.b64 {%0, %1}, %2;" : "=f"(lo), "=f"(hi) : "l"(v));
}
__device__ __forceinline__ unsigned long long fma2(unsigned long long a,
                                                   unsigned long long b,
                                                   unsigned long long c) {
    unsigned long long d;
    asm("fma.rn.f32x2 %0, %1, %2, %3;" : "=l"(d) : "l"(a), "l"(b), "l"(c));
    return d;
}

// ---------------------------------------------------------------------------
// Both chamfer directions in ONE launch: dir = blockIdx.z.
// Per jj (8 pairs): 3 LDS.64 + 8 FFMA2 + 8 FMNMX.
// Register policy (learned R4/R8): NO launch_bounds clamp — clamping spills.
// Natural pressure is lowered instead via partial unroll (4) of the jj loop,
// which bounds the batched live LDS.64 temps that were driving regs to 68.
// ---------------------------------------------------------------------------
__global__ void k_pass(const float* __restrict__ pt1,
                       const float* __restrict__ pt2) {
    const int n = blockIdx.y, tile = blockIdx.x, tid = threadIdx.x;
    const int dir = blockIdx.z;
    const int tx = tid & 15, ty = tid >> 4;

    const float* q = dir ? pt2 : pt1;
    const float* r = dir ? pt1 : pt2;

    __shared__ unsigned long long sA[BR], sB[BR], sC[BR];
    __shared__ float2 sQ[BQ];
    __shared__ float  sRed[16];

    const float2* qp = reinterpret_cast<const float2*>(q) + n * P + tile * BQ;
    const float2* rp = reinterpret_cast<const float2*>(r) + n * P;

    if (tid < BQ) sQ[tid] = qp[tid];
    float2 ycur = rp[tid];               // prefetch chunk 0
    __syncthreads();

    unsigned long long m2a[4], m2b[4];
    float rmin[8];
    #pragma unroll
    for (int p = 0; p < 4; p++) {
        float2 xa = sQ[ty * 8 + 2 * p];
        float2 xb = sQ[ty * 8 + 2 * p + 1];
        m2a[p] = pack2(-2.0f * xa.x, -2.0f * xb.x);
        m2b[p] = pack2(-2.0f * xa.y, -2.0f * xb.y);
    }
    #pragma unroll
    for (int i = 0; i < 8; i++) rmin[i] = 3.402823466e38f;

    for (int jc = 0; jc < NCHUNK; jc++) {
        __syncthreads();                 // consumers done with previous chunk
        sA[tid] = pack2(ycur.x, ycur.x);
        sB[tid] = pack2(ycur.y, ycur.y);
        float yy = fmaf(ycur.x, ycur.x, ycur.y * ycur.y);
        sC[tid] = pack2(yy, yy);
        if (jc + 1 < NCHUNK) ycur = rp[(jc + 1) * BR + tid];  // overlap LDG
        __syncthreads();

        #pragma unroll 4
        for (int jj = 0; jj < BR / 16; jj++) {
            const int c = jj * 16 + tx;  // 8B stride -> conflict-free/broadcast
            const unsigned long long ya = sA[c];
            const unsigned long long yb = sB[c];
            const unsigned long long yc = sC[c];
            #pragma unroll
            for (int p = 0; p < 4; p++) {
                unsigned long long u2 = fma2(m2a[p], ya, yc);
                u2 = fma2(m2b[p], yb, u2);
                float u0, u1;
                unpack2(u2, u0, u1);
                rmin[2 * p]     = fminf(rmin[2 * p], u0);
                rmin[2 * p + 1] = fminf(rmin[2 * p + 1], u1);
            }
        }
    }

    // epilogue: min across the 16 tx lanes of each ty group; x2 recomputed here
    float rs = 0.0f;
    #pragma unroll
    for (int i = 0; i < 8; i++) {
        float v = rmin[i];
        #pragma unroll
        for (int off = 8; off >= 1; off >>= 1)
            v = fminf(v, __shfl_xor_sync(0xffffffffu, v, off, 16));
        if (tx == 0) {
            float2 x = sQ[ty * 8 + i];
            float x2 = fmaf(x.x, x.x, x.y * x.y);
            rs += sqrtf(fmaxf(x2 + v, EPSF));
        }
    }
    if (tx == 0) sRed[ty] = rs;
    __syncthreads();
    if (tid == 0) {
        float s = 0.0f;
        #pragma unroll
        for (int t = 0; t < 16; t++) s += sRed[t];
        (dir ? g_sum2 : g_sum1)[n * 32 + tile] = s;
    }
}

// ---------------------------------------------------------------------------
// Finalize stage 1: one block per object (mask + per-object masked cost).
// ---------------------------------------------------------------------------
__global__ void k_final1(const float* __restrict__ pt2, float* __restrict__ unused) {
    __shared__ float sred[256];
    const int n = blockIdx.x, tid = threadIdx.x;

    float s = 0.0f;
    const float4* p = reinterpret_cast<const float4*>(pt2 + n * P * 2);
    #pragma unroll
    for (int i = 0; i < (P * 2 / 4) / 256; i++) {   // 8 independent loads
        float4 v = p[i * 256 + tid];
        s += (v.x + v.y) + (v.z + v.w);
    }
    sred[tid] = s;
    __syncthreads();
    #pragma unroll
    for (int st = 128; st > 0; st >>= 1) {
        if (tid < st) sred[tid] += sred[tid + st];
        __syncthreads();
    }
    if (tid == 0) {
        float mask = sred[0];
        float s1 = 0.0f, s2 = 0.0f;
        #pragma unroll
        for (int t = 0; t < 32; t++) {
            s1 += g_sum1[n * 32 + t];
            s2 += g_sum2[n * 32 + t];
        }
        g_cost[n] = (mask >= 0.0f) ? 0.5f * (s1 + s2) * (1.0f / P) : 0.0f;
    }
}

// Finalize stage 2: sum 16 per-object costs.
__global__ void k_final2(float* __restrict__ out) {
    if (threadIdx.x == 0) {
        float s = 0.0f;
        #pragma unroll
        for (int t = 0; t < NOBJ; t++) s += g_cost[t];
        out[0] = s * (1.0f / NOBJ);
    }
}

// ---------------------------------------------------------------------------
extern "C" void kernel_launch(void* const* d_in, const int* in_sizes, int n_in,
                              void* d_out, int out_size) {
    const float* pt1 = reinterpret_cast<const float*>(d_in[0]);
    const float* pt2 = reinterpret_cast<const float*>(d_in[1]);
    float* out = reinterpret_cast<float*>(d_out);
    (void)in_sizes; (void)n_in; (void)out_size;

    dim3 grid(P / BQ, NOBJ, 2);   // (32, 16, 2) — both directions, one launch
    k_pass<<<grid, 256>>>(pt1, pt2);
    k_final1<<<NOBJ, 256>>>(pt2, out);
    k_final2<<<1, 32>>>(out);
}

// round 12
// speedup vs baseline: 1.6759x; 1.0552x over previous
#include <cuda_runtime.h>
#include <cuda_bf16.h>
#include <cstdint>

// Fixed shapes: [16, 4096, 2] fp32 both inputs
#define NOBJ 16
#define P    4096
#define BQ   128      // queries per CTA
#define BR   256      // refs staged per chunk
#define NCHUNK (P/BR)
#define EPSF 1e-12f

// Scratch (allocation-free)
static __device__ float g_sum1[NOBJ * 32];
static __device__ float g_sum2[NOBJ * 32];
static __device__ float g_cost[NOBJ];

// ---- packed fp32x2 helpers (FFMA2 is PTX-only; ptxas won't auto-fuse) ----
__device__ __forceinline__ unsigned long long pack2(float lo, float hi) {
    unsigned long long r;
    asm("mov.b64 %0, {%1, %2};" : "=l"(r) : "f"(lo), "f"(hi));
    return r;
}
__device__ __forceinline__ void unpack2(unsigned long long v, float& lo, float& hi) {
    asm("mov.b64 {%0, %1}, %2;" : "=f"(lo), "=f"(hi) : "l"(v));
}
__device__ __forceinline__ unsigned long long fma2(unsigned long long a,
                                                   unsigned long long b,
                                                   unsigned long long c) {
    unsigned long long d;
    asm("fma.rn.f32x2 %0, %1, %2, %3;" : "=l"(d) : "l"(a), "l"(b), "l"(c));
    return d;
}

// ---------------------------------------------------------------------------
// Both chamfer directions in ONE launch: dir = blockIdx.z.
// R12 change vs R11 (single lever): ref staging merged so the inner loop does
// 2 LDS (1x LDS.128 + 1x LDS.64) instead of 3x LDS.64 per jj — targets the
// suspected LSU-wavefront binder. Everything else identical to R11:
// unroll 4, NO launch_bounds clamp (R4/R8: clamping spills).
//   sAB[c] = (yx,yx,yy,yy) float4  -> low u64 = ya-dup, high u64 = yb-dup
//   sC[c]  = (y2,y2) u64
// ---------------------------------------------------------------------------
__global__ void k_pass(const float* __restrict__ pt1,
                       const float* __restrict__ pt2) {
    const int n = blockIdx.y, tile = blockIdx.x, tid = threadIdx.x;
    const int dir = blockIdx.z;
    const int tx = tid & 15, ty = tid >> 4;

    const float* q = dir ? pt2 : pt1;
    const float* r = dir ? pt1 : pt2;

    __shared__ float4 sAB[BR];
    __shared__ unsigned long long sC[BR];
    __shared__ float2 sQ[BQ];
    __shared__ float  sRed[16];

    const float2* qp = reinterpret_cast<const float2*>(q) + n * P + tile * BQ;
    const float2* rp = reinterpret_cast<const float2*>(r) + n * P;

    if (tid < BQ) sQ[tid] = qp[tid];
    float2 ycur = rp[tid];               // prefetch chunk 0
    __syncthreads();

    unsigned long long m2a[4], m2b[4];
    float rmin[8];
    #pragma unroll
    for (int p = 0; p < 4; p++) {
        float2 xa = sQ[ty * 8 + 2 * p];
        float2 xb = sQ[ty * 8 + 2 * p + 1];
        m2a[p] = pack2(-2.0f * xa.x, -2.0f * xb.x);
        m2b[p] = pack2(-2.0f * xa.y, -2.0f * xb.y);
    }
    #pragma unroll
    for (int i = 0; i < 8; i++) rmin[i] = 3.402823466e38f;

    for (int jc = 0; jc < NCHUNK; jc++) {
        __syncthreads();                 // consumers done with previous chunk
        sAB[tid] = make_float4(ycur.x, ycur.x, ycur.y, ycur.y);
        float yy = fmaf(ycur.x, ycur.x, ycur.y * ycur.y);
        sC[tid] = pack2(yy, yy);
        if (jc + 1 < NCHUNK) ycur = rp[(jc + 1) * BR + tid];  // overlap LDG
        __syncthreads();

        #pragma unroll 4
        for (int jj = 0; jj < BR / 16; jj++) {
            const int c = jj * 16 + tx;  // conflict-free (16 unique per warp)
            float4 v = sAB[c];
            unsigned long long ya, yb;
            asm("mov.b64 %0, {%2, %3}; mov.b64 %1, {%4, %5};"
                : "=l"(ya), "=l"(yb)
                : "f"(v.x), "f"(v.y), "f"(v.z), "f"(v.w));
            const unsigned long long yc = sC[c];
            #pragma unroll
            for (int p = 0; p < 4; p++) {
                unsigned long long u2 = fma2(m2a[p], ya, yc);
                u2 = fma2(m2b[p], yb, u2);
                float u0, u1;
                unpack2(u2, u0, u1);
                rmin[2 * p]     = fminf(rmin[2 * p], u0);
                rmin[2 * p + 1] = fminf(rmin[2 * p + 1], u1);
            }
        }
    }

    // epilogue: min across the 16 tx lanes of each ty group; x2 recomputed here
    float rs = 0.0f;
    #pragma unroll
    for (int i = 0; i < 8; i++) {
        float v = rmin[i];
        #pragma unroll
        for (int off = 8; off >= 1; off >>= 1)
            v = fminf(v, __shfl_xor_sync(0xffffffffu, v, off, 16));
        if (tx == 0) {
            float2 x = sQ[ty * 8 + i];
            float x2 = fmaf(x.x, x.x, x.y * x.y);
            rs += sqrtf(fmaxf(x2 + v, EPSF));
        }
    }
    if (tx == 0) sRed[ty] = rs;
    __syncthreads();
    if (tid == 0) {
        float s = 0.0f;
        #pragma unroll
        for (int t = 0; t < 16; t++) s += sRed[t];
        (dir ? g_sum2 : g_sum1)[n * 32 + tile] = s;
    }
}

// ---------------------------------------------------------------------------
// Finalize stage 1: one block per object (mask + per-object masked cost).
// ---------------------------------------------------------------------------
__global__ void k_final1(const float* __restrict__ pt2, float* __restrict__ unused) {
    __shared__ float sred[256];
    const int n = blockIdx.x, tid = threadIdx.x;

    float s = 0.0f;
    const float4* p = reinterpret_cast<const float4*>(pt2 + n * P * 2);
    #pragma unroll
    for (int i = 0; i < (P * 2 / 4) / 256; i++) {   // 8 independent loads
        float4 v = p[i * 256 + tid];
        s += (v.x + v.y) + (v.z + v.w);
    }
    sred[tid] = s;
    __syncthreads();
    #pragma unroll
    for (int st = 128; st > 0; st >>= 1) {
        if (tid < st) sred[tid] += sred[tid + st];
        __syncthreads();
    }
    if (tid == 0) {
        float mask = sred[0];
        float s1 = 0.0f, s2 = 0.0f;
        #pragma unroll
        for (int t = 0; t < 32; t++) {
            s1 += g_sum1[n * 32 + t];
            s2 += g_sum2[n * 32 + t];
        }
        g_cost[n] = (mask >= 0.0f) ? 0.5f * (s1 + s2) * (1.0f / P) : 0.0f;
    }
}

// Finalize stage 2: sum 16 per-object costs.
__global__ void k_final2(float* __restrict__ out) {
    if (threadIdx.x == 0) {
        float s = 0.0f;
        #pragma unroll
        for (int t = 0; t < NOBJ; t++) s += g_cost[t];
        out[0] = s * (1.0f / NOBJ);
    }
}

// ---------------------------------------------------------------------------
extern "C" void kernel_launch(void* const* d_in, const int* in_sizes, int n_in,
                              void* d_out, int out_size) {
    const float* pt1 = reinterpret_cast<const float*>(d_in[0]);
    const float* pt2 = reinterpret_cast<const float*>(d_in[1]);
    float* out = reinterpret_cast<float*>(d_out);
    (void)in_sizes; (void)n_in; (void)out_size;

    dim3 grid(P / BQ, NOBJ, 2);   // (32, 16, 2) — both directions, one launch
    k_pass<<<grid, 256>>>(pt1, pt2);
    k_final1<<<NOBJ, 256>>>(pt2, out);
    k_final2<<<1, 32>>>(out);
}